// round 6
// baseline (speedup 1.0000x reference)
#include <cuda_runtime.h>

// Problem constants (fixed-shape problem)
#define NB      32
#define NSITES  65536
#define NNGB    13
#define DIM     3
#define NG      48
#define KDIM    (NG * DIM)             // 144
#define NPREP   16
#define ROWS_PER_PREP (KDIM / NPREP)   // 9

// Scratch (device-global: allocation-free rule)
__device__ __align__(16) float g_InT[NSITES * NB];   // 8 MB, site-major transpose
__device__ float g_Wpart[NPREP][DIM * NNGB];
__device__ float g_Wmean[DIM * NNGB];

// packed f32x2 FMA: d = a*b + d elementwise on float pairs in b64 regs
__device__ __forceinline__ void ffma2(unsigned long long& d,
                                      unsigned long long a,
                                      unsigned long long b) {
    asm("fma.rn.f32x2 %0, %1, %2, %0;" : "+l"(d) : "l"(a), "l"(b));
}

// ---------------------------------------------------------------------------
// Kernel 1: partial Wmean. 16 blocks x 320 threads; block p handles gdiags
// rows [9p, 9p+9). B[k][j] = wtVC[k%3][GnnPerms[k/3][j]].
// ---------------------------------------------------------------------------
__global__ __launch_bounds__(320)
void prep_kernel(const float* __restrict__ wtVC,
                 const float* __restrict__ gdiags,
                 const int*   __restrict__ GnnPerms) {
    __shared__ float B[KDIM][NNGB];
    __shared__ float sW[DIM * NNGB];
    int tid = threadIdx.x;

    if (tid < DIM * NNGB) sW[tid] = 0.f;
    for (int i = tid; i < KDIM * NNGB; i += 320) {
        int k = i / NNGB, j = i % NNGB;
        B[k][j] = wtVC[(k % 3) * NNGB + GnnPerms[(k / 3) * NNGB + j]];
    }
    __syncthreads();

    int w = tid >> 5, lane = tid & 31;
    if (w < ROWS_PER_PREP) {
        int r = blockIdx.x * ROWS_PER_PREP + w;
        float acc[NNGB];
        #pragma unroll
        for (int j = 0; j < NNGB; j++) acc[j] = 0.f;
        for (int k = lane; k < KDIM; k += 32) {            // coalesced row read
            float gv = gdiags[r * KDIM + k];
            #pragma unroll
            for (int j = 0; j < NNGB; j++) acc[j] += gv * B[k][j];
        }
        #pragma unroll
        for (int j = 0; j < NNGB; j++) {
            #pragma unroll
            for (int off = 16; off > 0; off >>= 1)
                acc[j] += __shfl_xor_sync(0xffffffffu, acc[j], off);
        }
        if (lane == 0) {
            int d = r % 3;
            #pragma unroll
            for (int j = 0; j < NNGB; j++)
                atomicAdd(&sW[d * NNGB + j], acc[j]);
        }
    }
    __syncthreads();
    if (tid < DIM * NNGB) g_Wpart[blockIdx.x][tid] = sW[tid];
}

// ---------------------------------------------------------------------------
// Kernel 2: transpose In (NB x NSITES) -> g_InT (NSITES x NB, fp32).
// Block 0 additionally reduces Wmean partials (prep done: stream order).
// ---------------------------------------------------------------------------
__global__ void transpose_kernel(const float* __restrict__ In) {
    __shared__ float tile[32][33];
    int tx = threadIdx.x, ty = threadIdx.y;
    int tid = ty * 32 + tx;

    if (blockIdx.x == 0 && tid < DIM * NNGB) {
        float s = 0.f;
        #pragma unroll
        for (int p = 0; p < NPREP; p++) s += g_Wpart[p][tid];
        g_Wmean[tid] = s * (1.0f / (float)NG);
    }

    int s0 = blockIdx.x * 32;
    tile[ty][tx] = In[ty * NSITES + s0 + tx];          // coalesced read
    __syncthreads();
    g_InT[(s0 + ty) * NB + tx] = tile[tx][ty];         // coalesced write
}

// ---------------------------------------------------------------------------
// Kernel 3: gather + contraction with packed f32x2 FMA.
// Block = 256 threads, 32 sites. Lane l: site = 4*w + (l>>3), chunk c = l&7
// (16B = batches 4c..4c+3, loaded as ulonglong2 = two pre-packed f32 pairs).
// Weights pre-packed {w,w} in smem -> 6 FFMA2 per j per thread, no packing ops.
// ---------------------------------------------------------------------------
__global__ __launch_bounds__(256, 6)
void conv_kernel(const int* __restrict__ NNsites, float* __restrict__ out) {
    __shared__ unsigned long long Wm2[DIM * NNGB];   // packed {w,w}
    __shared__ int   sidx[NNGB][32];
    __shared__ float sout[DIM][NB][33];   // pad 33 -> conflict-free scalar STS

    int tid = threadIdx.x;
    int s0  = blockIdx.x * 32;

    if (tid < DIM * NNGB) {
        unsigned int wb = __float_as_uint(g_Wmean[tid]);
        Wm2[tid] = ((unsigned long long)wb << 32) | wb;
    }
    for (int i = tid; i < NNGB * 32; i += 256) {
        int j = i >> 5, si = i & 31;
        sidx[j][si] = NNsites[j * NSITES + s0 + si];   // coalesced
    }
    __syncthreads();

    int w    = tid >> 5;
    int l    = tid & 31;
    int site = (w << 2) + (l >> 3);   // 0..31
    int c    = l & 7;                 // 16B chunk -> batches 4c..4c+3

    const ulonglong2* __restrict__ InT2 = (const ulonglong2*)g_InT;

    // acc[d][p]: dim d, pair p (batches 4c+2p, 4c+2p+1); bit pattern 0 == (0.f,0.f)
    unsigned long long acc[DIM][2] = {{0ull,0ull},{0ull,0ull},{0ull,0ull}};

    #pragma unroll
    for (int j = 0; j < NNGB; j++) {
        int        t = sidx[j][site];
        ulonglong2 v = __ldg(&InT2[t * 8 + c]);      // 128B-line gather, 16B/lane
        #pragma unroll
        for (int d = 0; d < DIM; d++) {
            unsigned long long w2 = Wm2[d * NNGB + j];   // broadcast LDS.64
            ffma2(acc[d][0], v.x, w2);
            ffma2(acc[d][1], v.y, w2);
        }
    }

    // Stage. Bank of sout[d][b][site] = (b + site) mod 32 (33 ≡ 1 mod 32);
    // lanes have b = 4c + const, site = 4w + r -> 4c + r distinct mod 32.
    int b0 = c << 2;
    #pragma unroll
    for (int d = 0; d < DIM; d++) {
        float2 p0 = *reinterpret_cast<float2*>(&acc[d][0]);
        float2 p1 = *reinterpret_cast<float2*>(&acc[d][1]);
        sout[d][b0 + 0][site] = p0.x;
        sout[d][b0 + 1][site] = p0.y;
        sout[d][b0 + 2][site] = p1.x;
        sout[d][b0 + 3][site] = p1.y;
    }
    __syncthreads();

    // Write out[b][d][s0+si]: 3072 floats/block, 12 per thread.
    // Warp spans 32 consecutive si with fixed (b,d): coalesced 128B stores.
    #pragma unroll
    for (int k = 0; k < 12; k++) {
        int idx  = tid + (k << 8);
        int si   = idx & 31;
        int rest = idx >> 5;          // 0..95
        int d    = rest % 3;
        int b    = rest / 3;
        out[(b * DIM + d) * NSITES + s0 + si] = sout[d][b][si];
    }
}

// ---------------------------------------------------------------------------
// Launch: In, wtVC, gdiags, GnnPerms, NNsites (metadata order)
// ---------------------------------------------------------------------------
extern "C" void kernel_launch(void* const* d_in, const int* in_sizes, int n_in,
                              void* d_out, int out_size) {
    const float* In       = (const float*)d_in[0];
    const float* wtVC     = (const float*)d_in[1];
    const float* gdiags   = (const float*)d_in[2];
    const int*   GnnPerms = (const int*)  d_in[3];
    const int*   NNsites  = (const int*)  d_in[4];
    float*       out      = (float*)d_out;

    prep_kernel<<<NPREP, 320>>>(wtVC, gdiags, GnnPerms);

    dim3 tblk(32, 32);
    transpose_kernel<<<NSITES / 32, tblk>>>(In);

    conv_kernel<<<NSITES / 32, 256>>>(NNsites, out);
}

// round 7
// speedup vs baseline: 1.4672x; 1.4672x over previous
#include <cuda_runtime.h>

// Problem constants (fixed-shape problem)
#define NB      32
#define NSITES  65536
#define NNGB    13
#define DIM     3
#define NG      48
#define KDIM    (NG * DIM)     // 144
#define NPREPB  16             // blocks that also compute Wmean partials
#define GRID    740            // <= guaranteed co-resident (occ 6 -> 888)
#define THREADS 256
#define NTILES  (NSITES / 32)  // 2048 tiles of 32 sites

// Scratch (device-global: allocation-free rule)
__device__ __align__(16) float g_InT[NSITES * NB];   // 8 MB site-major transpose
__device__ float    g_Wpart[NPREPB][DIM * NNGB];
__device__ unsigned g_ticketA, g_ticketB, g_barrier, g_done;  // zero-init, self-reset

// Shared memory byte layout (single buffer, phase-disjoint):
//  conv : Wm@0 (160B) | sidx@160 (13*32*4=1664B) | sout@1824 (3*1064*4=12768B)
//  prep : B@0 (144*13*4=7488B) | sW@7488 (160B)
//  trans: tile@7648 (32*33*4=4224B)
#define SMEM_BYTES 14592

__global__ __launch_bounds__(THREADS, 6)
void fused_kernel(const float* __restrict__ In,
                  const float* __restrict__ wtVC,
                  const float* __restrict__ gdiags,
                  const int*   __restrict__ GnnPerms,
                  const int*   __restrict__ NNsites,
                  float*       __restrict__ out) {
    __shared__ __align__(16) unsigned char s_raw[SMEM_BYTES];
    __shared__ unsigned s_t;
    float* s_f  = (float*)s_raw;
    int tid  = threadIdx.x;
    int w    = tid >> 5;
    int lane = tid & 31;

    // ---------------- Phase A0: Wmean partials (last 16 blocks only) --------
    if (blockIdx.x >= GRID - NPREPB) {
        int p = blockIdx.x - (GRID - NPREPB);
        float* B  = s_f;             // [144][13]
        float* sW = s_f + 1872;      // 39 accumulators (at byte 7488)
        if (tid < DIM * NNGB) sW[tid] = 0.f;
        for (int i = tid; i < KDIM * NNGB; i += THREADS) {
            int k = i / NNGB, j = i % NNGB;
            B[i] = wtVC[(k % 3) * NNGB + GnnPerms[(k / 3) * NNGB + j]];
        }
        __syncthreads();
        for (int rl = w; rl < 9; rl += 8) {          // 9 rows, 8 warps
            int r = p * 9 + rl;
            float acc[NNGB];
            #pragma unroll
            for (int j = 0; j < NNGB; j++) acc[j] = 0.f;
            for (int k = lane; k < KDIM; k += 32) {  // coalesced row read
                float gv = gdiags[r * KDIM + k];
                #pragma unroll
                for (int j = 0; j < NNGB; j++) acc[j] += gv * B[k * NNGB + j];
            }
            #pragma unroll
            for (int j = 0; j < NNGB; j++) {
                #pragma unroll
                for (int o = 16; o > 0; o >>= 1)
                    acc[j] += __shfl_xor_sync(0xffffffffu, acc[j], o);
            }
            if (lane == 0) {
                int d = r % 3;
                #pragma unroll
                for (int j = 0; j < NNGB; j++)
                    atomicAdd(&sW[d * NNGB + j], acc[j]);
            }
        }
        __syncthreads();
        if (tid < DIM * NNGB) g_Wpart[p][tid] = sW[tid];
    }

    // ---------------- Phase A1: ticketed transpose --------------------------
    {
        float (*tile)[33] = (float(*)[33])(s_raw + 7648);
        for (;;) {
            __syncthreads();                         // protect s_t + tile reuse
            if (tid == 0) s_t = atomicAdd(&g_ticketA, 1);
            __syncthreads();
            unsigned t = s_t;
            if (t >= NTILES) break;
            int s0 = t * 32;
            #pragma unroll
            for (int r = 0; r < 4; r++) {
                int b = w + 8 * r;
                tile[b][lane] = In[b * NSITES + s0 + lane];     // coalesced
            }
            __syncthreads();
            #pragma unroll
            for (int r = 0; r < 4; r++) {
                int sl = w + 8 * r;
                g_InT[(s0 + sl) * NB + lane] = tile[lane][sl];  // coalesced
            }
        }
    }

    // ---------------- Grid barrier (all 740 blocks co-resident) -------------
    __syncthreads();
    if (tid == 0) {
        __threadfence();                 // release our g_InT / g_Wpart writes
        atomicAdd(&g_barrier, 1);
        while (*((volatile unsigned*)&g_barrier) < GRID) __nanosleep(64);
        __threadfence();                 // acquire others' writes
    }
    __syncthreads();

    // ---------------- Phase B: ticketed gather+contraction -------------------
    float* Wm   = s_f;                        // 39 floats
    int*   sidx = (int*)(s_raw + 160);        // [13][32]
    float* sout = (float*)(s_raw + 1824);     // [3][1064]: d*1064 + b*33 + si

    if (tid < DIM * NNGB) {
        float s = 0.f;
        #pragma unroll
        for (int p = 0; p < NPREPB; p++) s += g_Wpart[p][tid];
        Wm[tid] = s * (1.0f / (float)NG);
    }

    int site = (w << 2) + (lane >> 3);   // 0..31
    int c    = lane & 7;                 // float4 chunk -> batches 4c..4c+3
    const float4* __restrict__ InT4 = (const float4*)g_InT;

    for (;;) {
        __syncthreads();                 // protect s_t + sidx/sout reuse; orders Wm
        if (tid == 0) s_t = atomicAdd(&g_ticketB, 1);
        __syncthreads();
        unsigned t = s_t;
        if (t >= NTILES) break;
        int s0 = t * 32;

        for (int i = tid; i < NNGB * 32; i += THREADS) {
            int j = i >> 5, si = i & 31;
            sidx[j * 32 + si] = NNsites[j * NSITES + s0 + si];   // coalesced
        }
        __syncthreads();

        float4 a0 = make_float4(0.f, 0.f, 0.f, 0.f);
        float4 a1 = a0, a2 = a0;
        #pragma unroll
        for (int j = 0; j < NNGB; j++) {
            int    tt = sidx[j * 32 + site];
            float4 v  = __ldg(&InT4[tt * 8 + c]);    // 128B-line gather
            float w0 = Wm[j], w1 = Wm[NNGB + j], w2 = Wm[2 * NNGB + j];
            a0.x += w0 * v.x; a0.y += w0 * v.y; a0.z += w0 * v.z; a0.w += w0 * v.w;
            a1.x += w1 * v.x; a1.y += w1 * v.y; a1.z += w1 * v.z; a1.w += w1 * v.w;
            a2.x += w2 * v.x; a2.y += w2 * v.y; a2.z += w2 * v.z; a2.w += w2 * v.w;
        }

        // Stage: addr word = 8d + 33b + site (mod 32) -> bank = (8d+b+site)%32.
        // Lanes per slot: b=4c+k, site=4w+r -> 4c+r distinct: conflict-free.
        int b0 = c << 2;
        sout[0 * 1064 + (b0 + 0) * 33 + site] = a0.x;
        sout[0 * 1064 + (b0 + 1) * 33 + site] = a0.y;
        sout[0 * 1064 + (b0 + 2) * 33 + site] = a0.z;
        sout[0 * 1064 + (b0 + 3) * 33 + site] = a0.w;
        sout[1 * 1064 + (b0 + 0) * 33 + site] = a1.x;
        sout[1 * 1064 + (b0 + 1) * 33 + site] = a1.y;
        sout[1 * 1064 + (b0 + 2) * 33 + site] = a1.z;
        sout[1 * 1064 + (b0 + 3) * 33 + site] = a1.w;
        sout[2 * 1064 + (b0 + 0) * 33 + site] = a2.x;
        sout[2 * 1064 + (b0 + 1) * 33 + site] = a2.y;
        sout[2 * 1064 + (b0 + 2) * 33 + site] = a2.z;
        sout[2 * 1064 + (b0 + 3) * 33 + site] = a2.w;
        __syncthreads();

        // 768 float4 = 3072 floats; 3 STG.128 per thread, fully coalesced.
        // Read banks: 8d term separates the 3 same-b rows -> conflict-free.
        #pragma unroll
        for (int k = 0; k < 3; k++) {
            int f4  = tid + (k << 8);    // 0..767
            int p   = f4 & 7;            // float4 chunk within row
            int row = f4 >> 3;           // 0..95 = b*3+d
            int d   = row % 3;
            int b   = row / 3;
            int si  = p << 2;
            float4 v;
            v.x = sout[d * 1064 + b * 33 + si];
            v.y = sout[d * 1064 + b * 33 + si + 1];
            v.z = sout[d * 1064 + b * 33 + si + 2];
            v.w = sout[d * 1064 + b * 33 + si + 3];
            ((float4*)(out + row * NSITES + s0))[p] = v;
        }
    }

    // ---------------- Counter self-reset (graph-replay safe) -----------------
    __syncthreads();
    if (tid == 0) {
        unsigned d = atomicAdd(&g_done, 1);
        if (d == GRID - 1) {
            g_ticketA = 0; g_ticketB = 0; g_barrier = 0;
            __threadfence();
            g_done = 0;
        }
    }
}

// ---------------------------------------------------------------------------
// Launch: In, wtVC, gdiags, GnnPerms, NNsites (metadata order). ONE kernel.
// ---------------------------------------------------------------------------
extern "C" void kernel_launch(void* const* d_in, const int* in_sizes, int n_in,
                              void* d_out, int out_size) {
    const float* In       = (const float*)d_in[0];
    const float* wtVC     = (const float*)d_in[1];
    const float* gdiags   = (const float*)d_in[2];
    const int*   GnnPerms = (const int*)  d_in[3];
    const int*   NNsites  = (const int*)  d_in[4];
    float*       out      = (float*)d_out;

    fused_kernel<<<GRID, THREADS>>>(In, wtVC, gdiags, GnnPerms, NNsites, out);
}

// round 9
// speedup vs baseline: 1.6729x; 1.1402x over previous
#include <cuda_runtime.h>

// Problem constants (fixed-shape problem)
#define NB      32
#define NSITES  65536
#define NNGB    13
#define DIM     3
#define NG      48
#define KDIM    (NG * DIM)             // 144
#define NPREP   16
#define ROWS_PER_PREP (KDIM / NPREP)   // 9

// Scratch (device-global: allocation-free rule)
__device__ __align__(16) float g_InT[NSITES * NB];   // 8 MB, site-major transpose
__device__ float g_Wpart[NPREP][DIM * NNGB];
__device__ float g_Wmean[DIM * NNGB];

// ---------------------------------------------------------------------------
// Kernel 1: partial Wmean. 16 blocks x 320 threads; block p handles gdiags
// rows [9p, 9p+9). B[k][j] = wtVC[k%3][GnnPerms[k/3][j]].
// ---------------------------------------------------------------------------
__global__ __launch_bounds__(320)
void prep_kernel(const float* __restrict__ wtVC,
                 const float* __restrict__ gdiags,
                 const int*   __restrict__ GnnPerms) {
    __shared__ float B[KDIM][NNGB];
    __shared__ float sW[DIM * NNGB];
    int tid = threadIdx.x;

    if (tid < DIM * NNGB) sW[tid] = 0.f;
    for (int i = tid; i < KDIM * NNGB; i += 320) {
        int k = i / NNGB, j = i % NNGB;
        B[k][j] = wtVC[(k % 3) * NNGB + GnnPerms[(k / 3) * NNGB + j]];
    }
    __syncthreads();

    int w = tid >> 5, lane = tid & 31;
    if (w < ROWS_PER_PREP) {
        int r = blockIdx.x * ROWS_PER_PREP + w;
        float acc[NNGB];
        #pragma unroll
        for (int j = 0; j < NNGB; j++) acc[j] = 0.f;
        for (int k = lane; k < KDIM; k += 32) {            // coalesced row read
            float gv = gdiags[r * KDIM + k];
            #pragma unroll
            for (int j = 0; j < NNGB; j++) acc[j] += gv * B[k][j];
        }
        #pragma unroll
        for (int j = 0; j < NNGB; j++) {
            #pragma unroll
            for (int off = 16; off > 0; off >>= 1)
                acc[j] += __shfl_xor_sync(0xffffffffu, acc[j], off);
        }
        if (lane == 0) {
            int d = r % 3;
            #pragma unroll
            for (int j = 0; j < NNGB; j++)
                atomicAdd(&sW[d * NNGB + j], acc[j]);
        }
    }
    __syncthreads();
    if (tid < DIM * NNGB) g_Wpart[blockIdx.x][tid] = sW[tid];
}

// ---------------------------------------------------------------------------
// Kernel 2: transpose In (NB x NSITES) -> g_InT (NSITES x NB, fp32).
// Block 0 additionally reduces Wmean partials (prep done: stream order).
// ---------------------------------------------------------------------------
__global__ void transpose_kernel(const float* __restrict__ In) {
    __shared__ float tile[32][33];
    int tx = threadIdx.x, ty = threadIdx.y;
    int tid = ty * 32 + tx;

    if (blockIdx.x == 0 && tid < DIM * NNGB) {
        float s = 0.f;
        #pragma unroll
        for (int p = 0; p < NPREP; p++) s += g_Wpart[p][tid];
        g_Wmean[tid] = s * (1.0f / (float)NG);
    }

    int s0 = blockIdx.x * 32;
    tile[ty][tx] = In[ty * NSITES + s0 + tx];          // coalesced read
    __syncthreads();
    g_InT[(s0 + ty) * NB + tx] = tile[tx][ty];         // coalesced write
}

// ---------------------------------------------------------------------------
// Kernel 3: gather + contraction, MLP-batched (round-8 resubmit: round-8's
// bench was an infra failure, this change was never measured).
// Block = 256 threads, 32 sites. Lane l: site = 4*w + (l>>3), chunk c = l&7
// (16B = batches 4c..4c+3). ALL 13 LDG.128 issued back-to-back into v[13]
// BEFORE any FMA -> 13-deep MLP per thread covers the ~250cyc L2-hit latency.
// occ target 3 -> 84-reg budget: 52 (v) + 12 (acc) + misc, no spills.
// ---------------------------------------------------------------------------
__global__ __launch_bounds__(256, 3)
void conv_kernel(const int* __restrict__ NNsites, float* __restrict__ out) {
    __shared__ float Wm[40];
    __shared__ int   sidx[NNGB][32];
    __shared__ float sout[DIM * 1064];    // d*1064 + b*33 + si : conflict-free

    int tid = threadIdx.x;
    int s0  = blockIdx.x * 32;

    if (tid < DIM * NNGB) Wm[tid] = g_Wmean[tid];
    for (int i = tid; i < NNGB * 32; i += 256) {
        int j = i >> 5, si = i & 31;
        sidx[j][si] = NNsites[j * NSITES + s0 + si];   // coalesced
    }
    __syncthreads();

    int w    = tid >> 5;
    int l    = tid & 31;
    int site = (w << 2) + (l >> 3);   // 0..31
    int c    = l & 7;                 // 16B chunk -> batches 4c..4c+3

    const float4* __restrict__ InT4 = (const float4*)g_InT;

    // 1) read all indices (broadcast LDS), 2) issue all 13 gathers, 3) FMA.
    int idx[NNGB];
    #pragma unroll
    for (int j = 0; j < NNGB; j++) idx[j] = sidx[j][site];

    float4 v[NNGB];
    #pragma unroll
    for (int j = 0; j < NNGB; j++) v[j] = __ldg(&InT4[idx[j] * 8 + c]);

    float4 a0 = make_float4(0.f, 0.f, 0.f, 0.f);
    float4 a1 = a0, a2 = a0;
    #pragma unroll
    for (int j = 0; j < NNGB; j++) {
        float w0 = Wm[j], w1 = Wm[NNGB + j], w2 = Wm[2 * NNGB + j];
        a0.x += w0 * v[j].x; a0.y += w0 * v[j].y; a0.z += w0 * v[j].z; a0.w += w0 * v[j].w;
        a1.x += w1 * v[j].x; a1.y += w1 * v[j].y; a1.z += w1 * v[j].z; a1.w += w1 * v[j].w;
        a2.x += w2 * v[j].x; a2.y += w2 * v[j].y; a2.z += w2 * v[j].z; a2.w += w2 * v[j].w;
    }

    // Stage: word = d*1064 + b*33 + site; bank = (8d + b + site) mod 32.
    // Per slot: b = 4c+k, site = 4w+r -> 4c+r distinct over 32 lanes. ✓
    int b0 = c << 2;
    sout[0 * 1064 + (b0 + 0) * 33 + site] = a0.x;
    sout[0 * 1064 + (b0 + 1) * 33 + site] = a0.y;
    sout[0 * 1064 + (b0 + 2) * 33 + site] = a0.z;
    sout[0 * 1064 + (b0 + 3) * 33 + site] = a0.w;
    sout[1 * 1064 + (b0 + 0) * 33 + site] = a1.x;
    sout[1 * 1064 + (b0 + 1) * 33 + site] = a1.y;
    sout[1 * 1064 + (b0 + 2) * 33 + site] = a1.z;
    sout[1 * 1064 + (b0 + 3) * 33 + site] = a1.w;
    sout[2 * 1064 + (b0 + 0) * 33 + site] = a2.x;
    sout[2 * 1064 + (b0 + 1) * 33 + site] = a2.y;
    sout[2 * 1064 + (b0 + 2) * 33 + site] = a2.z;
    sout[2 * 1064 + (b0 + 3) * 33 + site] = a2.w;
    __syncthreads();

    // 768 float4 = 3072 floats; 3 STG.128 per thread, fully coalesced.
    #pragma unroll
    for (int k = 0; k < 3; k++) {
        int f4  = tid + (k << 8);    // 0..767
        int p   = f4 & 7;            // float4 chunk within (b,d) row
        int row = f4 >> 3;           // 0..95 = b*3+d
        int d   = row % 3;
        int b   = row / 3;
        int si  = p << 2;
        float4 o;
        o.x = sout[d * 1064 + b * 33 + si];
        o.y = sout[d * 1064 + b * 33 + si + 1];
        o.z = sout[d * 1064 + b * 33 + si + 2];
        o.w = sout[d * 1064 + b * 33 + si + 3];
        ((float4*)(out + row * NSITES + s0))[p] = o;
    }
}

// ---------------------------------------------------------------------------
// Launch: In, wtVC, gdiags, GnnPerms, NNsites (metadata order)
// ---------------------------------------------------------------------------
extern "C" void kernel_launch(void* const* d_in, const int* in_sizes, int n_in,
                              void* d_out, int out_size) {
    const float* In       = (const float*)d_in[0];
    const float* wtVC     = (const float*)d_in[1];
    const float* gdiags   = (const float*)d_in[2];
    const int*   GnnPerms = (const int*)  d_in[3];
    const int*   NNsites  = (const int*)  d_in[4];
    float*       out      = (float*)d_out;

    prep_kernel<<<NPREP, 320>>>(wtVC, gdiags, GnnPerms);

    dim3 tblk(32, 32);
    transpose_kernel<<<NSITES / 32, tblk>>>(In);

    conv_kernel<<<NSITES / 32, 256>>>(NNsites, out);
}

// round 11
// speedup vs baseline: 1.6749x; 1.0012x over previous
#include <cuda_runtime.h>
#include <cuda_fp16.h>

// Problem constants (fixed-shape problem)
#define NB      32
#define NSITES  65536
#define NNGB    13
#define DIM     3
#define NG      48
#define KDIM    (NG * DIM)             // 144
#define NPREP   16
#define ROWS_PER_PREP (KDIM / NPREP)   // 9
#define SITES_PER_BLK 64
#define CONV_THREADS  256

// Scratch (device-global: allocation-free rule)
__device__ __align__(16) __half g_InTh[NSITES * NB];  // 4 MB fp16 site-major transpose
__device__ float g_Wpart[NPREP][DIM * NNGB];
__device__ float g_Wmean[DIM * NNGB];

// ---------------------------------------------------------------------------
// Kernel 1: partial Wmean. 16 blocks x 320 threads; block p handles gdiags
// rows [9p, 9p+9). B[k][j] = wtVC[k%3][GnnPerms[k/3][j]].
// ---------------------------------------------------------------------------
__global__ __launch_bounds__(320)
void prep_kernel(const float* __restrict__ wtVC,
                 const float* __restrict__ gdiags,
                 const int*   __restrict__ GnnPerms) {
    __shared__ float B[KDIM][NNGB];
    __shared__ float sW[DIM * NNGB];
    int tid = threadIdx.x;

    if (tid < DIM * NNGB) sW[tid] = 0.f;
    for (int i = tid; i < KDIM * NNGB; i += 320) {
        int k = i / NNGB, j = i % NNGB;
        B[k][j] = wtVC[(k % 3) * NNGB + GnnPerms[(k / 3) * NNGB + j]];
    }
    __syncthreads();

    int w = tid >> 5, lane = tid & 31;
    if (w < ROWS_PER_PREP) {
        int r = blockIdx.x * ROWS_PER_PREP + w;
        float acc[NNGB];
        #pragma unroll
        for (int j = 0; j < NNGB; j++) acc[j] = 0.f;
        for (int k = lane; k < KDIM; k += 32) {            // coalesced row read
            float gv = gdiags[r * KDIM + k];
            #pragma unroll
            for (int j = 0; j < NNGB; j++) acc[j] += gv * B[k][j];
        }
        #pragma unroll
        for (int j = 0; j < NNGB; j++) {
            #pragma unroll
            for (int off = 16; off > 0; off >>= 1)
                acc[j] += __shfl_xor_sync(0xffffffffu, acc[j], off);
        }
        if (lane == 0) {
            int d = r % 3;
            #pragma unroll
            for (int j = 0; j < NNGB; j++)
                atomicAdd(&sW[d * NNGB + j], acc[j]);
        }
    }
    __syncthreads();
    if (tid < DIM * NNGB) g_Wpart[blockIdx.x][tid] = sW[tid];
}

// ---------------------------------------------------------------------------
// Kernel 2: transpose In (NB x NSITES fp32) -> g_InTh (NSITES x NB fp16).
// Block 0 additionally reduces Wmean partials (prep done: stream order).
// ---------------------------------------------------------------------------
__global__ void transpose_kernel(const float* __restrict__ In) {
    __shared__ float tile[32][33];
    int tx = threadIdx.x, ty = threadIdx.y;
    int tid = ty * 32 + tx;

    if (blockIdx.x == 0 && tid < DIM * NNGB) {
        float s = 0.f;
        #pragma unroll
        for (int p = 0; p < NPREP; p++) s += g_Wpart[p][tid];
        g_Wmean[tid] = s * (1.0f / (float)NG);
    }

    int s0 = blockIdx.x * 32;
    tile[ty][tx] = In[ty * NSITES + s0 + tx];              // coalesced read
    __syncthreads();
    g_InTh[(s0 + ty) * NB + tx] = __float2half(tile[tx][ty]);  // coalesced 2B
}

// ---------------------------------------------------------------------------
// Kernel 3: gather + contraction. fp16 gather, fp32 accumulate, MLP-batched.
// Block = 256 threads, 64 sites. Lane l: site = 8*w + (l>>2), chunk c = l&3
// (16B = batches 8c..8c+7). One LDG.128 covers 8 sites (8 x 64B rows, full
// 32B sectors). ALL 13 loads issued back-to-back into v[13] before any
// convert/FMA (r9's proven MLP batching). occ cap 2 -> 128-reg budget:
// 52 (v) + 24 (acc) + misc, guaranteed no spills (r4 trap avoided).
// Epilogue: direct scalar STG — lanes of one store = 4 rows x 8 consecutive
// sites = four FULL 32B sectors; no smem staging, no 2nd syncthreads.
// ---------------------------------------------------------------------------
__global__ __launch_bounds__(CONV_THREADS, 2)
void conv_kernel(const int* __restrict__ NNsites, float* __restrict__ out) {
    __shared__ float Wm[40];
    __shared__ int   sidx[NNGB][SITES_PER_BLK];

    int tid = threadIdx.x;
    int s0  = blockIdx.x * SITES_PER_BLK;

    if (tid < DIM * NNGB) Wm[tid] = g_Wmean[tid];
    for (int i = tid; i < NNGB * SITES_PER_BLK; i += CONV_THREADS) {
        int j = i >> 6, si = i & 63;
        sidx[j][si] = NNsites[j * NSITES + s0 + si];    // coalesced
    }
    __syncthreads();

    int w    = tid >> 5;
    int l    = tid & 31;
    int site = (w << 3) + (l >> 2);   // 0..63
    int c    = l & 3;                 // 16B chunk -> batches 8c..8c+7

    const uint4* __restrict__ InT16 = (const uint4*)g_InTh;

    // 1) all indices (broadcast LDS), 2) all 13 LDG.128 back-to-back, 3) math.
    int idx[NNGB];
    #pragma unroll
    for (int j = 0; j < NNGB; j++) idx[j] = sidx[j][site];

    uint4 v[NNGB];
    #pragma unroll
    for (int j = 0; j < NNGB; j++) v[j] = __ldg(&InT16[idx[j] * 4 + c]);

    float a0[8], a1[8], a2[8];        // dims x batches 8c..8c+7 (fp32)
    #pragma unroll
    for (int q = 0; q < 8; q++) { a0[q] = 0.f; a1[q] = 0.f; a2[q] = 0.f; }

    #pragma unroll
    for (int j = 0; j < NNGB; j++) {
        float2 p[4];
        p[0] = __half22float2(*reinterpret_cast<const __half2*>(&v[j].x));
        p[1] = __half22float2(*reinterpret_cast<const __half2*>(&v[j].y));
        p[2] = __half22float2(*reinterpret_cast<const __half2*>(&v[j].z));
        p[3] = __half22float2(*reinterpret_cast<const __half2*>(&v[j].w));
        float w0 = Wm[j], w1 = Wm[NNGB + j], w2 = Wm[2 * NNGB + j];
        #pragma unroll
        for (int q = 0; q < 4; q++) {
            a0[2*q]   += w0 * p[q].x; a0[2*q+1] += w0 * p[q].y;
            a1[2*q]   += w1 * p[q].x; a1[2*q+1] += w1 * p[q].y;
            a2[2*q]   += w2 * p[q].x; a2[2*q+1] += w2 * p[q].y;
        }
    }

    // Direct stores: out[(b*3+d)*NSITES + s0 + site], b = 8c + m.
    // Per instruction: 4 b-rows x 8 consecutive sites -> 4 full 32B sectors.
    int b0 = c << 3;
    #pragma unroll
    for (int m = 0; m < 8; m++) {
        int b = b0 + m;
        out[(b * DIM + 0) * NSITES + s0 + site] = a0[m];
        out[(b * DIM + 1) * NSITES + s0 + site] = a1[m];
        out[(b * DIM + 2) * NSITES + s0 + site] = a2[m];
    }
}

// ---------------------------------------------------------------------------
// Launch: In, wtVC, gdiags, GnnPerms, NNsites (metadata order)
// ---------------------------------------------------------------------------
extern "C" void kernel_launch(void* const* d_in, const int* in_sizes, int n_in,
                              void* d_out, int out_size) {
    const float* In       = (const float*)d_in[0];
    const float* wtVC     = (const float*)d_in[1];
    const float* gdiags   = (const float*)d_in[2];
    const int*   GnnPerms = (const int*)  d_in[3];
    const int*   NNsites  = (const int*)  d_in[4];
    float*       out      = (float*)d_out;

    prep_kernel<<<NPREP, 320>>>(wtVC, gdiags, GnnPerms);

    dim3 tblk(32, 32);
    transpose_kernel<<<NSITES / 32, tblk>>>(In);

    conv_kernel<<<NSITES / SITES_PER_BLK, CONV_THREADS>>>(NNsites, out);
}